// round 7
// baseline (speedup 1.0000x reference)
#include <cuda_runtime.h>
#include <cstdint>

#define THREADS 128
#define TILE 128
#define BPS 7

// ---------- PTX helpers ----------
__device__ __forceinline__ uint32_t smem_u32(const void* p) {
    uint32_t a;
    asm("{ .reg .u64 t; cvta.to.shared.u64 t, %1; cvt.u32.u64 %0, t; }"
        : "=r"(a) : "l"(p));
    return a;
}
__device__ __forceinline__ void bulk_s2g(void* gdst, uint32_t ssrc, uint32_t bytes) {
    asm volatile("cp.async.bulk.global.shared::cta.bulk_group [%0], [%1], %2;"
                 :: "l"(gdst), "r"(ssrc), "r"(bytes) : "memory");
}

// ---------- FK math ----------
__device__ __forceinline__ void build_R(float ex, float ey, float ez, float* R) {
    float sx, cx, sy, cy, sz, cz;
    __sincosf(ex, &sx, &cx);
    __sincosf(ey, &sy, &cy);
    __sincosf(ez, &sz, &cz);
    float sxsy = sx * sy;
    float cxsy = cx * sy;
    R[0] = cy * cz;                   R[1] = -cy * sz;                  R[2] = sy;
    R[3] = fmaf(sxsy, cz,  cx * sz);  R[4] = fmaf(-sxsy, sz, cx * cz);  R[5] = -sx * cy;
    R[6] = fmaf(-cxsy, cz, sx * sz);  R[7] = fmaf(cxsy, sz,  sx * cz);  R[8] = cx * cy;
}
__device__ __forceinline__ void chain_step(float* M, float* p,
                                           float ex, float ey, float ez, float L) {
    float R[9];
    build_R(ex, ey, ez, R);
    float T[9];
#pragma unroll
    for (int r = 0; r < 3; r++)
#pragma unroll
        for (int c = 0; c < 3; c++)
            T[3*r+c] = fmaf(M[3*r+0], R[c],
                       fmaf(M[3*r+1], R[3+c], M[3*r+2] * R[6+c]));
#pragma unroll
    for (int i = 0; i < 9; i++) M[i] = T[i];
    p[0] = fmaf(L, M[6], p[0]);
    p[1] = fmaf(L, M[7], p[1]);
    p[2] = fmaf(L, M[8], p[2]);
}
__device__ __forceinline__ void root_step(float* M, float* p,
                                          float ex, float ey, float ez, float L) {
    build_R(ex, ey, ez, M);
    p[0] = L * M[6]; p[1] = L * M[7]; p[2] = L * M[8];
}

// ---------- kernel ----------
__global__ void __launch_bounds__(THREADS, BPS)
fk_kernel(const float* __restrict__ euler,
          const float* __restrict__ blen,
          float* __restrict__ out, int N, int nTiles) {
    // Single dual-use buffer: 51 floats/thread (odd stride -> conflict-free).
    // Staging writes euler into slot offsets 0..47; compute prefetches bone
    // i+1's euler (slot offset 3i+3) before writing joint i+1's position to
    // the SAME offset -> after compute the buffer IS the tile's output image.
    __shared__ __align__(16) float sbuf[TILE * 51];

    int tid = threadIdx.x;
    int G = gridDim.x;
    int b = blockIdx.x;
    int nT = (b < nTiles) ? (nTiles - b + G - 1) / G : 0;

#pragma unroll 1
    for (int it = 0; it < nT; it++) {
        int base = (b + it * G) * TILE;
        int cnt = N - base; if (cnt > TILE) cnt = TILE;
        bool full = (cnt == TILE);

        // early blen prefetch (global, independent of smem hazards)
        const float4* l4 = reinterpret_cast<const float4*>(blen) + (size_t)(base + tid) * 4;
        bool act = tid < cnt;
        float4 Lq0, Lq1;
        if (act) { Lq0 = l4[0]; Lq1 = l4[1]; }

        const float4* e4 = reinterpret_cast<const float4*>(euler) + (size_t)base * 12;

        if (full) {
            // ---- pipelined staging: LDG rounds overlap store-drain + each other
            float4 v0[4], v1[4], v2[4];
#pragma unroll
            for (int j = 0; j < 4; j++) v0[j] = e4[tid + j * THREADS];
            // gate: previous tile's bulk store must have consumed the buffer
            if (tid == 0)
                asm volatile("cp.async.bulk.wait_group.read 0;" ::: "memory");
            __syncthreads();
#pragma unroll
            for (int j = 0; j < 4; j++) v1[j] = e4[tid + (4 + j) * THREADS];
#pragma unroll
            for (int j = 0; j < 4; j++) {
                int i = tid + j * THREADS;
                int s = i / 12, k = (i % 12) * 4;
                float* d = sbuf + s * 51 + k;
                d[0] = v0[j].x; d[1] = v0[j].y; d[2] = v0[j].z; d[3] = v0[j].w;
            }
#pragma unroll
            for (int j = 0; j < 4; j++) v2[j] = e4[tid + (8 + j) * THREADS];
#pragma unroll
            for (int j = 0; j < 4; j++) {
                int i = tid + (4 + j) * THREADS;
                int s = i / 12, k = (i % 12) * 4;
                float* d = sbuf + s * 51 + k;
                d[0] = v1[j].x; d[1] = v1[j].y; d[2] = v1[j].z; d[3] = v1[j].w;
            }
#pragma unroll
            for (int j = 0; j < 4; j++) {
                int i = tid + (8 + j) * THREADS;
                int s = i / 12, k = (i % 12) * 4;
                float* d = sbuf + s * 51 + k;
                d[0] = v2[j].x; d[1] = v2[j].y; d[2] = v2[j].z; d[3] = v2[j].w;
            }
        } else {
            if (tid == 0)
                asm volatile("cp.async.bulk.wait_group.read 0;" ::: "memory");
            __syncthreads();
            int total4 = cnt * 12;
            for (int i = tid; i < total4; i += THREADS) {
                float4 v = e4[i];
                int s = i / 12, k = (i % 12) * 4;
                float* d = sbuf + s * 51 + k;
                d[0] = v.x; d[1] = v.y; d[2] = v.z; d[3] = v.w;
            }
        }
        __syncthreads();   // staging complete

        if (act) {
            float* slot = sbuf + tid * 51;
            float ex = slot[0], ey = slot[1], ez = slot[2];
            slot[0] = 0.0f; slot[1] = 0.0f; slot[2] = 0.0f;  // root

            float M[9], p[3], M8[9], p8[3];
            float nx, ny, nz;

#define PRE(i)   { nx = slot[3*(i)+3]; ny = slot[3*(i)+4]; nz = slot[3*(i)+5]; }
#define EMIT(i)  { slot[3*(i)+3] = p[0]; slot[3*(i)+4] = p[1]; slot[3*(i)+5] = p[2]; \
                   ex = nx; ey = ny; ez = nz; }

            // chain 0 -> 1 -> 2 -> 3
            PRE(0);  root_step (M, p, ex, ey, ez, Lq0.x); EMIT(0);
            PRE(1);  chain_step(M, p, ex, ey, ez, Lq0.y); EMIT(1);
            PRE(2);  chain_step(M, p, ex, ey, ez, Lq0.z); EMIT(2);
            // chain 0 -> 4 -> 5 -> 6
            PRE(3);  root_step (M, p, ex, ey, ez, Lq0.w); EMIT(3);
            float4 Lq2 = l4[2];
            PRE(4);  chain_step(M, p, ex, ey, ez, Lq1.x); EMIT(4);
            PRE(5);  chain_step(M, p, ex, ey, ez, Lq1.y); EMIT(5);
            // chain 0 -> 7 -> 8
            PRE(6);  root_step (M, p, ex, ey, ez, Lq1.z); EMIT(6);
            PRE(7);  chain_step(M, p, ex, ey, ez, Lq1.w); EMIT(7);
#pragma unroll
            for (int q = 0; q < 9; q++) M8[q] = M[q];
            p8[0] = p[0]; p8[1] = p[1]; p8[2] = p[2];
            float4 Lq3 = l4[3];
            // 8 -> 9 -> 10
            PRE(8);  chain_step(M, p, ex, ey, ez, Lq2.x); EMIT(8);
            PRE(9);  chain_step(M, p, ex, ey, ez, Lq2.y); EMIT(9);
            // 8 -> 11 -> 12 -> 13
#pragma unroll
            for (int q = 0; q < 9; q++) M[q] = M8[q];
            p[0] = p8[0]; p[1] = p8[1]; p[2] = p8[2];
            PRE(10); chain_step(M, p, ex, ey, ez, Lq2.z); EMIT(10);
            PRE(11); chain_step(M, p, ex, ey, ez, Lq2.w); EMIT(11);
            PRE(12); chain_step(M, p, ex, ey, ez, Lq3.x); EMIT(12);
            // 8 -> 14 -> 15 -> 16
#pragma unroll
            for (int q = 0; q < 9; q++) M[q] = M8[q];
            p[0] = p8[0]; p[1] = p8[1]; p[2] = p8[2];
            PRE(13); chain_step(M, p, ex, ey, ez, Lq3.y); EMIT(13);
            PRE(14); chain_step(M, p, ex, ey, ez, Lq3.z); EMIT(14);
            chain_step(M, p, ex, ey, ez, Lq3.w);
            slot[48] = p[0]; slot[49] = p[1]; slot[50] = p[2];
#undef PRE
#undef EMIT
            // fallback for a non-16B-multiple tail: store directly
            if (((unsigned)cnt * 204u & 15u) != 0u) {
                float* op = out + (size_t)(base + tid) * 51;
#pragma unroll
                for (int q = 0; q < 51; q++) op[q] = slot[q];
            }
        }
        __syncthreads();   // all position writes done

        if (tid == 0) {
            uint32_t obytes = (uint32_t)cnt * 204u;
            if ((obytes & 15u) == 0u) {
                asm volatile("fence.proxy.async.shared::cta;" ::: "memory");
                bulk_s2g(out + (size_t)base * 51, smem_u32(sbuf), obytes);
                asm volatile("cp.async.bulk.commit_group;" ::: "memory");
                // drain deferred to next iteration's staging gate
            }
        }
    }
    if (tid == 0)
        asm volatile("cp.async.bulk.wait_group 0;" ::: "memory");
}

extern "C" void kernel_launch(void* const* d_in, const int* in_sizes, int n_in,
                              void* d_out, int out_size) {
    const float* euler = (const float*)d_in[0];  // (N,16,3) f32
    const float* blen  = (const float*)d_in[1];  // (N,16,1) f32
    float* out = (float*)d_out;                  // (N,17,3) f32
    int N = in_sizes[0] / 48;
    int nTiles = (N + TILE - 1) / TILE;
    int grid = 152 * BPS;                        // GB300: 152 SMs
    if (grid > nTiles) grid = nTiles;
    fk_kernel<<<grid, THREADS>>>(euler, blen, out, N, nTiles);
}